// round 13
// baseline (speedup 1.0000x reference)
#include <cuda_runtime.h>
#include <cuda_fp16.h>
#include <cstdint>

#define B_  4
#define T_  2048
#define C_  1024
#define H_  128
#define BT_ (B_ * T_)
#define UPB 144      // units per batch, chunk=4
#define NUNITS (B_ * UPB)   // 576

// Static device scratch (allocation-free). Q/K/V/x/Wt/Opart held as fp16.
__device__ __half g_Xh[BT_ * C_];
__device__ __half g_Q[BT_ * H_];
__device__ __half g_K[BT_ * H_];
__device__ __half g_V[BT_ * H_];
__device__ __half g_Wt[3 * H_ * C_];          // W transposed [w][n][k]
__device__ __half g_Opart[NUNITS * 64 * H_];  // unnormalized partial O (fp16)
__device__ float g_ml[NUNITS * 64 * 2];       // per-row (m, l) fp32
__device__ int   g_cnt[B_ * 32];              // per-(b,qt) completion counters

// ---------------------------------------------------------------------------
// Helpers
// ---------------------------------------------------------------------------
__device__ __forceinline__ void mma_f16(float* d, const uint32_t* a,
                                        uint32_t b0, uint32_t b1) {
    asm volatile(
        "mma.sync.aligned.m16n8k16.row.col.f32.f16.f16.f32 "
        "{%0,%1,%2,%3}, {%4,%5,%6,%7}, {%8,%9}, {%0,%1,%2,%3};"
        : "+f"(d[0]), "+f"(d[1]), "+f"(d[2]), "+f"(d[3])
        : "r"(a[0]), "r"(a[1]), "r"(a[2]), "r"(a[3]), "r"(b0), "r"(b1));
}
__device__ __forceinline__ void ldsm4(uint32_t* r, uint32_t addr) {
    asm volatile("ldmatrix.sync.aligned.m8n8.x4.shared.b16 {%0,%1,%2,%3}, [%4];"
                 : "=r"(r[0]), "=r"(r[1]), "=r"(r[2]), "=r"(r[3]) : "r"(addr));
}
__device__ __forceinline__ void ldsm4t(uint32_t* r, uint32_t addr) {
    asm volatile("ldmatrix.sync.aligned.m8n8.x4.trans.shared.b16 {%0,%1,%2,%3}, [%4];"
                 : "=r"(r[0]), "=r"(r[1]), "=r"(r[2]), "=r"(r[3]) : "r"(addr));
}
__device__ __forceinline__ uint32_t smem_u32(const void* p) {
    uint32_t a;
    asm("{ .reg .u64 t; cvta.to.shared.u64 t, %1; cvt.u32.u64 %0, t; }"
        : "=r"(a) : "l"(p));
    return a;
}

#define CP16(dst, src) \
    asm volatile("cp.async.cg.shared.global [%0], [%1], 16;" \
                 :: "r"(dst), "l"(src) : "memory")
#define CPCOMMIT() asm volatile("cp.async.commit_group;" ::: "memory")
#define CPWAIT(n)  asm volatile("cp.async.wait_group %0;" :: "n"(n) : "memory")

// Half-unit swizzled layout. Chunk = 8 halves (16B); chunk idx XOR (row&7).
__device__ __forceinline__ int swzh(int r, int rowlen, int c8) {
    return r * rowlen + ((c8 ^ (r & 7)) << 3);
}

// ---------------------------------------------------------------------------
// Kernel 0: fused prep — x fp32->fp16, W transpose+convert, counter zero.
// ---------------------------------------------------------------------------
#define PREP_XBLOCKS (BT_ * C_ / (256 * 4))   // 8192

__global__ __launch_bounds__(256) void prep(const float* __restrict__ x,
                                            const float* __restrict__ Wq,
                                            const float* __restrict__ Wk,
                                            const float* __restrict__ Wv) {
    if (blockIdx.x < PREP_XBLOCKS) {
        if (blockIdx.x == 0 && threadIdx.x < B_ * 32)
            g_cnt[threadIdx.x] = 0;
        const int i = (blockIdx.x * 256 + threadIdx.x) * 4;
        float4 v = *(const float4*)&x[i];
        *(__half2*)&g_Xh[i]     = __floats2half2_rn(v.x, v.y);
        *(__half2*)&g_Xh[i + 2] = __floats2half2_rn(v.z, v.w);
    } else {
        __shared__ float tile[32][33];
        const int bi = blockIdx.x - PREP_XBLOCKS;   // 0..383
        const int w = bi >> 7;
        const int rest = bi & 127;
        const int k0 = (rest >> 2) * 32, n0 = (rest & 3) * 32;
        const float* __restrict__ W = (w == 0) ? Wq : (w == 1) ? Wk : Wv;
        const int tx = threadIdx.x & 31, ty = threadIdx.x >> 5;
#pragma unroll
        for (int i = 0; i < 32; i += 8)
            tile[ty + i][tx] = W[(k0 + ty + i) * H_ + n0 + tx];
        __syncthreads();
#pragma unroll
        for (int i = 0; i < 32; i += 8)
            g_Wt[w * H_ * C_ + (n0 + ty + i) * C_ + k0 + tx] =
                __float2half_rn(tile[tx][ty + i]);
    }
}

// ---------------------------------------------------------------------------
// Kernel 1: fused QKV projection, FP16 m16n8k16 + ldmatrix + 3-stage cp.async.
// CTA 64(M) x 384(N), grid 128. 8 warps 2M x 4N, warp tile 32x96.
// ---------------------------------------------------------------------------
#define PJ_STG 28672                    // halves per stage
#define PJ_SMEM (3 * PJ_STG * 2)        // 172032 B

__global__ __launch_bounds__(256, 1) void proj_mma()
{
    extern __shared__ __half smh[];
    const uint32_t sbase = smem_u32(smh);
    const int tid = threadIdx.x, wid = tid >> 5, lane = tid & 31;
    const int g = lane >> 2, tig = lane & 3;
    const int wm = (wid & 1) << 5;
    const int wn = (wid >> 1) * 96;
    const int m0 = blockIdx.x * 64;

    const int ar = tid >> 2, ac = (tid & 3) << 1;
    const __half* srcA = g_Xh + (m0 + ar) * C_ + ac * 8;
    const __half* srcB = g_Wt + ar * C_ + ac * 8;

    const int arow = wm + (lane & 15);
    const int brow = wn + (lane & 7) + ((lane >> 4) << 3);
    const int bksel = (lane >> 3) & 1;

    float acc[2][12][4];
#pragma unroll
    for (int mt = 0; mt < 2; mt++)
#pragma unroll
        for (int nt = 0; nt < 12; nt++)
#pragma unroll
            for (int i = 0; i < 4; i++) acc[mt][nt][i] = 0.f;

#pragma unroll
    for (int s = 0; s < 2; s++) {
        const uint32_t st = sbase + (uint32_t)(s * PJ_STG) * 2;
        const int k0 = s * 64;
#pragma unroll
        for (int i = 0; i < 2; i++)
            CP16(st + (uint32_t)swzh(ar, 64, ac + i) * 2, srcA + k0 + i * 8);
#pragma unroll
        for (int i = 0; i < 6; i++) {
            int r = ar + i * 64;
#pragma unroll
            for (int j = 0; j < 2; j++)
                CP16(st + (uint32_t)(4096 + swzh(r, 64, ac + j)) * 2,
                     srcB + i * 64 * C_ + k0 + j * 8);
        }
        CPCOMMIT();
    }

    for (int s = 0; s < 16; s++) {
        CPWAIT(1);
        __syncthreads();
        const uint32_t st = sbase + (uint32_t)((s % 3) * PJ_STG) * 2;
#pragma unroll
        for (int kk = 0; kk < 64; kk += 16) {
            uint32_t a[2][4];
#pragma unroll
            for (int mt = 0; mt < 2; mt++)
                ldsm4(a[mt], st + (uint32_t)swzh(arow + mt * 16, 64,
                                                (kk >> 3) + (lane >> 4)) * 2);
#pragma unroll
            for (int p = 0; p < 6; p++) {
                uint32_t b[4];
                ldsm4(b, st + (uint32_t)(4096 + swzh(brow + p * 16, 64,
                                                    (kk >> 3) + bksel)) * 2);
                mma_f16(acc[0][2 * p],     a[0], b[0], b[1]);
                mma_f16(acc[1][2 * p],     a[1], b[0], b[1]);
                mma_f16(acc[0][2 * p + 1], a[0], b[2], b[3]);
                mma_f16(acc[1][2 * p + 1], a[1], b[2], b[3]);
            }
        }
        if (s + 2 < 16) {
            const uint32_t stn = sbase + (uint32_t)(((s + 2) % 3) * PJ_STG) * 2;
            const int k0 = (s + 2) * 64;
#pragma unroll
            for (int i = 0; i < 2; i++)
                CP16(stn + (uint32_t)swzh(ar, 64, ac + i) * 2, srcA + k0 + i * 8);
#pragma unroll
            for (int i = 0; i < 6; i++) {
                int r = ar + i * 64;
#pragma unroll
                for (int j = 0; j < 2; j++)
                    CP16(stn + (uint32_t)(4096 + swzh(r, 64, ac + j)) * 2,
                         srcB + i * 64 * C_ + k0 + j * 8);
            }
        }
        CPCOMMIT();
    }

#pragma unroll
    for (int mt = 0; mt < 2; mt++)
#pragma unroll
        for (int nt = 0; nt < 12; nt++) {
            int n = wn + nt * 8 + tig * 2;
            __half* outp = (n < 128) ? g_Q : (n < 256) ? g_K : g_V;
            int col = n & 127;
            int r = m0 + wm + mt * 16 + g;
            *(__half2*)&outp[r * H_ + col] =
                __floats2half2_rn(acc[mt][nt][0], acc[mt][nt][1]);
            *(__half2*)&outp[(r + 8) * H_ + col] =
                __floats2half2_rn(acc[mt][nt][2], acc[mt][nt][3]);
        }
}

// ---------------------------------------------------------------------------
// Kernel 2: attention partial + FUSED merge. Split-K chunk=4, 576 units
// heavy-first, 2 CTAs/SM, FP16 m16n8k16, in-register softmax. The last unit
// to finish a (b,qt) tile (device atomics + fences) merges partials -> out.
// smem (halves): Q 8192 | K 8192 | V 8192 | P 4096 = 28672 h + 256 f stats.
// ---------------------------------------------------------------------------
#define AQ_  0
#define AK_  8192
#define AV_  16384
#define AP_  24576
#define AST_ 28672   // half offset of float stats
#define ATTN_SMEM (28672 * 2 + 256 * 4)   // 58368 B

__global__ __launch_bounds__(256, 2) void attn_part(float* __restrict__ out) {
    extern __shared__ __half smh[];
    __half* smP = smh + AP_;
    float* smS = (float*)(smh + AST_);   // [row][4]: max h0,h1, sum h0,h1
    const uint32_t sbase = smem_u32(smh);

    // heavy-first: reverse unit order (high qt first)
    const int idx = (NUNITS - 1) - blockIdx.x;
    const int b = idx / UPB;
    const int u = idx % UPB;
    int a = (int)((sqrtf(2.f * u + 1.f) - 1.f) * 0.5f);
    if (2 * (a + 1) * (a + 2) <= u) a++;
    if (2 * a * (a + 1) > u) a--;
    const int rem = u - 2 * a * (a + 1);
    const int qt = 4 * a + rem / (a + 1);
    const int ch = rem - (rem / (a + 1)) * (a + 1);
    const int m0 = qt * 64;
    const int t0 = ch * 4;
    const int t1 = min(t0 + 4, qt + 1);

    const __half* __restrict__ Qg = g_Q + (b * T_ + m0) * H_;
    const __half* __restrict__ Kg = g_K + b * T_ * H_;
    const __half* __restrict__ Vg = g_V + b * T_ * H_;

    const int tid = threadIdx.x;
    const int wid = tid >> 5, lane = tid & 31;
    const int g = lane >> 2, tig = lane & 3;
    const int wm   = (wid & 3) << 4;
    const int wns  = (wid >> 2) << 5;
    const int wno  = (wid >> 2) << 6;
    const int half_ = wid >> 2;
    const int rA = wm + g, rB = wm + g + 8;

    const int arow = wm + (lane & 15);
    const int brow = wns + (lane & 7) + ((lane >> 4) << 3);
    const int bksel = (lane >> 3) & 1;
    const int vrow16 = lane & 15;
    const int vnsel = lane >> 4;

    const int crow = tid >> 2, cc = (tid & 3) << 2;

    // prologue: async Q, async K(t0)
#pragma unroll
    for (int i = 0; i < 4; i++)
        CP16(sbase + (uint32_t)(AQ_ + swzh(crow, 128, cc + i)) * 2,
             Qg + crow * H_ + (cc + i) * 8);
    CPCOMMIT();
#pragma unroll
    for (int i = 0; i < 4; i++)
        CP16(sbase + (uint32_t)(AK_ + swzh(crow, 128, cc + i)) * 2,
             Kg + (t0 * 64 + crow) * H_ + (cc + i) * 8);
    CPCOMMIT();

    float m_run2[2] = {-1e30f, -1e30f};
    float l_run2[2] = {0.f, 0.f};
    float oacc[8][4];
#pragma unroll
    for (int nt = 0; nt < 8; nt++)
#pragma unroll
        for (int i = 0; i < 4; i++) oacc[nt][i] = 0.f;

    const float inv_scale = 0.03125f;  // C^-0.5

    for (int t = t0; t < t1; t++) {
        __syncthreads();   // PV(t-1) done -> V buffer + P free
#pragma unroll
        for (int i = 0; i < 4; i++)
            CP16(sbase + (uint32_t)(AV_ + swzh(crow, 128, cc + i)) * 2,
                 Vg + (t * 64 + crow) * H_ + (cc + i) * 8);
        CPCOMMIT();
        CPWAIT(1);         // K(t) (and Q) arrived
        __syncthreads();

        // S = Q @ K^T  (warp 16x32), K=128 in 8 k16 steps
        float sacc[4][4];
#pragma unroll
        for (int nt = 0; nt < 4; nt++)
#pragma unroll
            for (int i = 0; i < 4; i++) sacc[nt][i] = 0.f;

#pragma unroll
        for (int kk = 0; kk < 128; kk += 16) {
            uint32_t aa[4];
            ldsm4(aa, sbase + (uint32_t)(AQ_ + swzh(arow, 128,
                                                    (kk >> 3) + (lane >> 4))) * 2);
#pragma unroll
            for (int p = 0; p < 2; p++) {
                uint32_t bb[4];
                ldsm4(bb, sbase + (uint32_t)(AK_ + swzh(brow + p * 16, 128,
                                                        (kk >> 3) + bksel)) * 2);
                mma_f16(sacc[2 * p],     aa, bb[0], bb[1]);
                mma_f16(sacc[2 * p + 1], aa, bb[2], bb[3]);
            }
        }

        // scale + causal mask in fragment layout
        const bool diag = (t == qt);
#pragma unroll
        for (int nt = 0; nt < 4; nt++) {
            int cn = wns + nt * 8 + tig * 2;
            sacc[nt][0] *= inv_scale;
            sacc[nt][1] *= inv_scale;
            sacc[nt][2] *= inv_scale;
            sacc[nt][3] *= inv_scale;
            if (diag) {
                if (cn > rA)     sacc[nt][0] = -1e30f;
                if (cn + 1 > rA) sacc[nt][1] = -1e30f;
                if (cn > rB)     sacc[nt][2] = -1e30f;
                if (cn + 1 > rB) sacc[nt][3] = -1e30f;
            }
        }

        // row max: quad shfl, then cross-half via smem stats
        float pmaxA = -1e30f, pmaxB = -1e30f;
#pragma unroll
        for (int nt = 0; nt < 4; nt++) {
            pmaxA = fmaxf(pmaxA, fmaxf(sacc[nt][0], sacc[nt][1]));
            pmaxB = fmaxf(pmaxB, fmaxf(sacc[nt][2], sacc[nt][3]));
        }
        pmaxA = fmaxf(pmaxA, __shfl_xor_sync(0xffffffffu, pmaxA, 1));
        pmaxA = fmaxf(pmaxA, __shfl_xor_sync(0xffffffffu, pmaxA, 2));
        pmaxB = fmaxf(pmaxB, __shfl_xor_sync(0xffffffffu, pmaxB, 1));
        pmaxB = fmaxf(pmaxB, __shfl_xor_sync(0xffffffffu, pmaxB, 2));
        if (tig == 0) {
            smS[rA * 4 + half_] = pmaxA;
            smS[rB * 4 + half_] = pmaxB;
        }
        __syncthreads();   // stats visible + all warps done reading smK

        if (t + 1 < t1) {  // prefetch K(t+1), overlaps softmax + PV
#pragma unroll
            for (int i = 0; i < 4; i++)
                CP16(sbase + (uint32_t)(AK_ + swzh(crow, 128, cc + i)) * 2,
                     Kg + ((t + 1) * 64 + crow) * H_ + (cc + i) * 8);
        }
        CPCOMMIT();

        float mxA = fmaxf(pmaxA, smS[rA * 4 + (1 - half_)]);
        float mxB = fmaxf(pmaxB, smS[rB * 4 + (1 - half_)]);
        float mnewA = fmaxf(m_run2[0], mxA);
        float mnewB = fmaxf(m_run2[1], mxB);
        float corrA = __expf(m_run2[0] - mnewA);
        float corrB = __expf(m_run2[1] - mnewB);
        m_run2[0] = mnewA; m_run2[1] = mnewB;

        float psumA = 0.f, psumB = 0.f;
#pragma unroll
        for (int nt = 0; nt < 4; nt++) {
            int cn = wns + nt * 8 + tig * 2;
            float p0 = __expf(sacc[nt][0] - mnewA);
            float p1 = __expf(sacc[nt][1] - mnewA);
            float p2 = __expf(sacc[nt][2] - mnewB);
            float p3 = __expf(sacc[nt][3] - mnewB);
            psumA += p0 + p1;
            psumB += p2 + p3;
            *(__half2*)&smP[swzh(rA, 64, cn >> 3) + (cn & 7)] =
                __floats2half2_rn(p0, p1);
            *(__half2*)&smP[swzh(rB, 64, cn >> 3) + (cn & 7)] =
                __floats2half2_rn(p2, p3);
        }
        psumA += __shfl_xor_sync(0xffffffffu, psumA, 1);
        psumA += __shfl_xor_sync(0xffffffffu, psumA, 2);
        psumB += __shfl_xor_sync(0xffffffffu, psumB, 1);
        psumB += __shfl_xor_sync(0xffffffffu, psumB, 2);
        if (tig == 0) {
            smS[rA * 4 + 2 + half_] = psumA;
            smS[rB * 4 + 2 + half_] = psumB;
        }
        if (t + 1 < t1) { CPWAIT(1); } else { CPWAIT(0); }  // V(t) arrived
        __syncthreads();

        l_run2[0] = l_run2[0] * corrA + psumA + smS[rA * 4 + 2 + (1 - half_)];
        l_run2[1] = l_run2[1] * corrB + psumB + smS[rB * 4 + 2 + (1 - half_)];

        // rescale O, then O += P @ V (warp 16x64), K=64 in 4 k16 steps
#pragma unroll
        for (int nt = 0; nt < 8; nt++) {
            oacc[nt][0] *= corrA; oacc[nt][1] *= corrA;
            oacc[nt][2] *= corrB; oacc[nt][3] *= corrB;
        }
#pragma unroll
        for (int kk = 0; kk < 64; kk += 16) {
            uint32_t aa[4];
            ldsm4(aa, sbase + (uint32_t)(AP_ + swzh(arow, 64,
                                                    (kk >> 3) + (lane >> 4))) * 2);
#pragma unroll
            for (int p = 0; p < 4; p++) {
                uint32_t bb[4];
                int vr = kk + vrow16;
                ldsm4t(bb, sbase + (uint32_t)(AV_ + swzh(vr, 128,
                                        (wno >> 3) + p * 2 + vnsel)) * 2);
                mma_f16(oacc[2 * p],     aa, bb[0], bb[1]);
                mma_f16(oacc[2 * p + 1], aa, bb[2], bb[3]);
            }
        }
    }

    // write unnormalized partials (fp16) + per-row (m, l)
    const int p = idx;
    if (tig == 0 && half_ == 0) {
        g_ml[(p * 64 + rA) * 2 + 0] = m_run2[0];
        g_ml[(p * 64 + rA) * 2 + 1] = l_run2[0];
        g_ml[(p * 64 + rB) * 2 + 0] = m_run2[1];
        g_ml[(p * 64 + rB) * 2 + 1] = l_run2[1];
    }
#pragma unroll
    for (int nt = 0; nt < 8; nt++) {
        int cc2 = wno + nt * 8 + tig * 2;
        *(__half2*)&g_Opart[(p * 64 + rA) * H_ + cc2] =
            __floats2half2_rn(oacc[nt][0], oacc[nt][1]);
        *(__half2*)&g_Opart[(p * 64 + rB) * H_ + cc2] =
            __floats2half2_rn(oacc[nt][2], oacc[nt][3]);
    }

    // ---- fused merge: the LAST unit of this (b, qt) merges partials ----
    __threadfence();                       // release our partials
    __shared__ int lastFlag;
    const int nch = a + 1;                 // total chunks for this qt
    if (tid == 0) {
        int old = atomicAdd(&g_cnt[b * 32 + qt], 1);
        lastFlag = (old == nch - 1) ? 1 : 0;
    }
    __syncthreads();
    if (lastFlag) {
        __threadfence();                   // acquire others' partials
        const int pbase = b * UPB + (a + 1) * (2 * a + (qt & 3));
        const int r = tid >> 2;            // 0..63
        const int c0 = (tid & 3) << 5;     // 0,32,64,96
        float wgt[8];
        float mmax = -1e30f;
        for (int c = 0; c < nch; c++)
            mmax = fmaxf(mmax, g_ml[((pbase + c) * 64 + r) * 2]);
        float l = 0.f;
        for (int c = 0; c < nch; c++) {
            wgt[c] = __expf(g_ml[((pbase + c) * 64 + r) * 2] - mmax);
            l += wgt[c] * g_ml[((pbase + c) * 64 + r) * 2 + 1];
        }
        const float invl = 1.f / l;
        const int orow = (b * T_ + m0 + r) * H_;
#pragma unroll
        for (int cb = 0; cb < 32; cb += 8) {
            float ac8[8] = {0.f, 0.f, 0.f, 0.f, 0.f, 0.f, 0.f, 0.f};
            for (int c = 0; c < nch; c++) {
                uint4 raw = *(const uint4*)
                    &g_Opart[((pbase + c) * 64 + r) * H_ + c0 + cb];
                const __half2* h = reinterpret_cast<const __half2*>(&raw);
#pragma unroll
                for (int j = 0; j < 4; j++) {
                    float2 f = __half22float2(h[j]);
                    ac8[2 * j]     += wgt[c] * f.x;
                    ac8[2 * j + 1] += wgt[c] * f.y;
                }
            }
            *(float4*)&out[orow + c0 + cb] =
                make_float4(ac8[0] * invl, ac8[1] * invl,
                            ac8[2] * invl, ac8[3] * invl);
            *(float4*)&out[orow + c0 + cb + 4] =
                make_float4(ac8[4] * invl, ac8[5] * invl,
                            ac8[6] * invl, ac8[7] * invl);
        }
    }
}

// ---------------------------------------------------------------------------
// Launch
// ---------------------------------------------------------------------------
extern "C" void kernel_launch(void* const* d_in, const int* in_sizes, int n_in,
                              void* d_out, int out_size) {
    const float* x  = (const float*)d_in[0];
    const float* Wq = (const float*)d_in[1];
    const float* Wk = (const float*)d_in[2];
    const float* Wv = (const float*)d_in[3];
    // d_in[4] = mask: tril by construction -> causal logic used directly.
    float* out = (float*)d_out;

    prep<<<PREP_XBLOCKS + 384, 256>>>(x, Wq, Wk, Wv);

    cudaFuncSetAttribute((const void*)proj_mma,
                         cudaFuncAttributeMaxDynamicSharedMemorySize, PJ_SMEM);
    proj_mma<<<BT_ / 64, 256, PJ_SMEM>>>();

    cudaFuncSetAttribute((const void*)attn_part,
                         cudaFuncAttributeMaxDynamicSharedMemorySize, ATTN_SMEM);
    attn_part<<<NUNITS, 256, ATTN_SMEM>>>(out);
}

// round 14
// speedup vs baseline: 1.1640x; 1.1640x over previous
#include <cuda_runtime.h>
#include <cuda_fp16.h>
#include <cstdint>

#define B_  4
#define T_  2048
#define C_  1024
#define H_  128
#define BT_ (B_ * T_)
#define UPB 144      // units per batch, chunk=4
#define NUNITS (B_ * UPB)   // 576

// Static device scratch (allocation-free). Q/K/V/Wt/Opart held as fp16.
__device__ __half g_Q[BT_ * H_];
__device__ __half g_K[BT_ * H_];
__device__ __half g_V[BT_ * H_];
__device__ __half g_Wt[3 * H_ * C_];          // W transposed [w][n][k]
__device__ __half g_Opart[NUNITS * 64 * H_];  // unnormalized partial O (fp16)
__device__ float g_ml[NUNITS * 64 * 2];       // per-row (m, l) fp32

// ---------------------------------------------------------------------------
// Helpers
// ---------------------------------------------------------------------------
__device__ __forceinline__ void mma_f16(float* d, const uint32_t* a,
                                        uint32_t b0, uint32_t b1) {
    asm volatile(
        "mma.sync.aligned.m16n8k16.row.col.f32.f16.f16.f32 "
        "{%0,%1,%2,%3}, {%4,%5,%6,%7}, {%8,%9}, {%0,%1,%2,%3};"
        : "+f"(d[0]), "+f"(d[1]), "+f"(d[2]), "+f"(d[3])
        : "r"(a[0]), "r"(a[1]), "r"(a[2]), "r"(a[3]), "r"(b0), "r"(b1));
}
__device__ __forceinline__ void ldsm4(uint32_t* r, uint32_t addr) {
    asm volatile("ldmatrix.sync.aligned.m8n8.x4.shared.b16 {%0,%1,%2,%3}, [%4];"
                 : "=r"(r[0]), "=r"(r[1]), "=r"(r[2]), "=r"(r[3]) : "r"(addr));
}
__device__ __forceinline__ void ldsm4t(uint32_t* r, uint32_t addr) {
    asm volatile("ldmatrix.sync.aligned.m8n8.x4.trans.shared.b16 {%0,%1,%2,%3}, [%4];"
                 : "=r"(r[0]), "=r"(r[1]), "=r"(r[2]), "=r"(r[3]) : "r"(addr));
}
__device__ __forceinline__ uint32_t smem_u32(const void* p) {
    uint32_t a;
    asm("{ .reg .u64 t; cvta.to.shared.u64 t, %1; cvt.u32.u64 %0, t; }"
        : "=r"(a) : "l"(p));
    return a;
}

#define CP16(dst, src) \
    asm volatile("cp.async.cg.shared.global [%0], [%1], 16;" \
                 :: "r"(dst), "l"(src) : "memory")
#define CPCOMMIT() asm volatile("cp.async.commit_group;" ::: "memory")
#define CPWAIT(n)  asm volatile("cp.async.wait_group %0;" :: "n"(n) : "memory")

// Half-unit swizzled layout. Chunk = 8 halves (16B); chunk idx XOR (row&7).
__device__ __forceinline__ int swzh(int r, int rowlen, int c8) {
    return r * rowlen + ((c8 ^ (r & 7)) << 3);
}

// ---------------------------------------------------------------------------
// Kernel 0: transpose W [C,H] -> g_Wt [w][H][C] fp16  (x conversion deleted —
// proj now consumes x fp32 directly)
// ---------------------------------------------------------------------------
__global__ void transpose_w(const float* __restrict__ Wq,
                            const float* __restrict__ Wk,
                            const float* __restrict__ Wv) {
    __shared__ float tile[32][33];
    const int w = blockIdx.z;
    const float* __restrict__ W = (w == 0) ? Wq : (w == 1) ? Wk : Wv;
    const int k0 = blockIdx.x * 32, n0 = blockIdx.y * 32;
    const int tx = threadIdx.x, ty = threadIdx.y;  // 32 x 8
#pragma unroll
    for (int i = 0; i < 32; i += 8)
        tile[ty + i][tx] = W[(k0 + ty + i) * H_ + n0 + tx];
    __syncthreads();
#pragma unroll
    for (int i = 0; i < 32; i += 8)
        g_Wt[w * H_ * C_ + (n0 + ty + i) * C_ + k0 + tx] =
            __float2half_rn(tile[tx][ty + i]);
}

// ---------------------------------------------------------------------------
// Kernel 1: fused QKV projection, FP16 m16n8k16 + ldmatrix.
// A (x fp32): LDG->cvt->STS, register-pipelined 2 stages ahead.
// B (Wt fp16): 3-stage cp.async (unchanged).
// CTA 64(M) x 384(N), grid 128. 8 warps 2M x 4N, warp tile 32x96.
// ---------------------------------------------------------------------------
#define PJ_STG 28672                    // halves per stage
#define PJ_SMEM (3 * PJ_STG * 2)        // 172032 B

__global__ __launch_bounds__(256, 1) void proj_mma(const float* __restrict__ x)
{
    extern __shared__ __half smh[];
    const uint32_t sbase = smem_u32(smh);
    const int tid = threadIdx.x, wid = tid >> 5, lane = tid & 31;
    const int g = lane >> 2, tig = lane & 3;
    const int wm = (wid & 1) << 5;
    const int wn = (wid >> 1) * 96;
    const int m0 = blockIdx.x * 64;

    const int ar = tid >> 2, ac = (tid & 3) << 1;       // A: row, chunk base
    const float* srcA = x + (m0 + ar) * C_ + ac * 8;    // fp32 source
    const __half* srcB = g_Wt + ar * C_ + ac * 8;

    const int arow = wm + (lane & 15);
    const int brow = wn + (lane & 7) + ((lane >> 4) << 3);
    const int bksel = (lane >> 3) & 1;

    float acc[2][12][4];
#pragma unroll
    for (int mt = 0; mt < 2; mt++)
#pragma unroll
        for (int nt = 0; nt < 12; nt++)
#pragma unroll
            for (int i = 0; i < 4; i++) acc[mt][nt][i] = 0.f;

    // A convert+store helper target addresses: swzh(ar, 64, ac+i), i=0,1
    // prologue: stages 0,1 — A direct LDG->cvt->STS, B via cp.async
#pragma unroll
    for (int s = 0; s < 2; s++) {
        __half* stp = smh + s * PJ_STG;
        const int k0 = s * 64;
#pragma unroll
        for (int i = 0; i < 2; i++) {
            float4 f0 = *(const float4*)(srcA + k0 + i * 8);
            float4 f1 = *(const float4*)(srcA + k0 + i * 8 + 4);
            __half2 h[4] = {__floats2half2_rn(f0.x, f0.y),
                            __floats2half2_rn(f0.z, f0.w),
                            __floats2half2_rn(f1.x, f1.y),
                            __floats2half2_rn(f1.z, f1.w)};
            *(uint4*)&stp[swzh(ar, 64, ac + i)] = *(uint4*)h;
        }
        const uint32_t st = sbase + (uint32_t)(s * PJ_STG) * 2;
#pragma unroll
        for (int i = 0; i < 6; i++) {
            int r = ar + i * 64;
#pragma unroll
            for (int j = 0; j < 2; j++)
                CP16(st + (uint32_t)(4096 + swzh(r, 64, ac + j)) * 2,
                     srcB + i * 64 * C_ + k0 + j * 8);
        }
        CPCOMMIT();
    }

    for (int s = 0; s < 16; s++) {
        // issue A(s+2) fp32 loads early (overlap with wait + MMA)
        float4 fa[4];
        if (s + 2 < 16) {
            const int k0 = (s + 2) * 64;
#pragma unroll
            for (int i = 0; i < 4; i++)
                fa[i] = *(const float4*)(srcA + k0 + i * 4);
        }
        CPWAIT(1);
        __syncthreads();
        const uint32_t st = sbase + (uint32_t)((s % 3) * PJ_STG) * 2;
#pragma unroll
        for (int kk = 0; kk < 64; kk += 16) {
            uint32_t a[2][4];
#pragma unroll
            for (int mt = 0; mt < 2; mt++)
                ldsm4(a[mt], st + (uint32_t)swzh(arow + mt * 16, 64,
                                                (kk >> 3) + (lane >> 4)) * 2);
#pragma unroll
            for (int p = 0; p < 6; p++) {
                uint32_t b[4];
                ldsm4(b, st + (uint32_t)(4096 + swzh(brow + p * 16, 64,
                                                    (kk >> 3) + bksel)) * 2);
                mma_f16(acc[0][2 * p],     a[0], b[0], b[1]);
                mma_f16(acc[1][2 * p],     a[1], b[0], b[1]);
                mma_f16(acc[0][2 * p + 1], a[0], b[2], b[3]);
                mma_f16(acc[1][2 * p + 1], a[1], b[2], b[3]);
            }
        }
        if (s + 2 < 16) {
            // A(s+2): convert + store into (s+2)%3 buffer (safe: != s%3)
            __half* stp = smh + ((s + 2) % 3) * PJ_STG;
#pragma unroll
            for (int i = 0; i < 2; i++) {
                __half2 h[4] = {__floats2half2_rn(fa[2 * i].x, fa[2 * i].y),
                                __floats2half2_rn(fa[2 * i].z, fa[2 * i].w),
                                __floats2half2_rn(fa[2 * i + 1].x, fa[2 * i + 1].y),
                                __floats2half2_rn(fa[2 * i + 1].z, fa[2 * i + 1].w)};
                *(uint4*)&stp[swzh(ar, 64, ac + i)] = *(uint4*)h;
            }
            // B(s+2) via cp.async
            const uint32_t stn = sbase + (uint32_t)(((s + 2) % 3) * PJ_STG) * 2;
            const int k0 = (s + 2) * 64;
#pragma unroll
            for (int i = 0; i < 6; i++) {
                int r = ar + i * 64;
#pragma unroll
                for (int j = 0; j < 2; j++)
                    CP16(stn + (uint32_t)(4096 + swzh(r, 64, ac + j)) * 2,
                         srcB + i * 64 * C_ + k0 + j * 8);
            }
        }
        CPCOMMIT();
    }

#pragma unroll
    for (int mt = 0; mt < 2; mt++)
#pragma unroll
        for (int nt = 0; nt < 12; nt++) {
            int n = wn + nt * 8 + tig * 2;
            __half* outp = (n < 128) ? g_Q : (n < 256) ? g_K : g_V;
            int col = n & 127;
            int r = m0 + wm + mt * 16 + g;
            *(__half2*)&outp[r * H_ + col] =
                __floats2half2_rn(acc[mt][nt][0], acc[mt][nt][1]);
            *(__half2*)&outp[(r + 8) * H_ + col] =
                __floats2half2_rn(acc[mt][nt][2], acc[mt][nt][3]);
        }
}

// ---------------------------------------------------------------------------
// Kernel 2: attention partial (proven round-12 config: split-K chunk=4,
// 576 units heavy-first, 2 CTAs/SM), FP16 m16n8k16, in-register softmax,
// V B-frags via ldmatrix.trans. Partials stored fp16.
// ---------------------------------------------------------------------------
#define AQ_  0
#define AK_  8192
#define AV_  16384
#define AP_  24576
#define AST_ 28672   // half offset of float stats
#define ATTN_SMEM (28672 * 2 + 256 * 4)   // 58368 B

__global__ __launch_bounds__(256, 2) void attn_part() {
    extern __shared__ __half smh[];
    __half* smP = smh + AP_;
    float* smS = (float*)(smh + AST_);   // [row][4]: max h0,h1, sum h0,h1
    const uint32_t sbase = smem_u32(smh);

    // heavy-first: reverse unit order (high qt first)
    const int idx = (NUNITS - 1) - blockIdx.x;
    const int b = idx / UPB;
    const int u = idx % UPB;
    int a = (int)((sqrtf(2.f * u + 1.f) - 1.f) * 0.5f);
    if (2 * (a + 1) * (a + 2) <= u) a++;
    if (2 * a * (a + 1) > u) a--;
    const int rem = u - 2 * a * (a + 1);
    const int qt = 4 * a + rem / (a + 1);
    const int ch = rem - (rem / (a + 1)) * (a + 1);
    const int m0 = qt * 64;
    const int t0 = ch * 4;
    const int t1 = min(t0 + 4, qt + 1);

    const __half* __restrict__ Qg = g_Q + (b * T_ + m0) * H_;
    const __half* __restrict__ Kg = g_K + b * T_ * H_;
    const __half* __restrict__ Vg = g_V + b * T_ * H_;

    const int tid = threadIdx.x;
    const int wid = tid >> 5, lane = tid & 31;
    const int g = lane >> 2, tig = lane & 3;
    const int wm   = (wid & 3) << 4;
    const int wns  = (wid >> 2) << 5;
    const int wno  = (wid >> 2) << 6;
    const int half_ = wid >> 2;
    const int rA = wm + g, rB = wm + g + 8;

    const int arow = wm + (lane & 15);
    const int brow = wns + (lane & 7) + ((lane >> 4) << 3);
    const int bksel = (lane >> 3) & 1;
    const int vrow16 = lane & 15;
    const int vnsel = lane >> 4;

    const int crow = tid >> 2, cc = (tid & 3) << 2;

    // prologue: async Q, async K(t0)
#pragma unroll
    for (int i = 0; i < 4; i++)
        CP16(sbase + (uint32_t)(AQ_ + swzh(crow, 128, cc + i)) * 2,
             Qg + crow * H_ + (cc + i) * 8);
    CPCOMMIT();
#pragma unroll
    for (int i = 0; i < 4; i++)
        CP16(sbase + (uint32_t)(AK_ + swzh(crow, 128, cc + i)) * 2,
             Kg + (t0 * 64 + crow) * H_ + (cc + i) * 8);
    CPCOMMIT();

    float m_run2[2] = {-1e30f, -1e30f};
    float l_run2[2] = {0.f, 0.f};
    float oacc[8][4];
#pragma unroll
    for (int nt = 0; nt < 8; nt++)
#pragma unroll
        for (int i = 0; i < 4; i++) oacc[nt][i] = 0.f;

    const float inv_scale = 0.03125f;  // C^-0.5

    for (int t = t0; t < t1; t++) {
        __syncthreads();   // PV(t-1) done -> V buffer + P free
#pragma unroll
        for (int i = 0; i < 4; i++)
            CP16(sbase + (uint32_t)(AV_ + swzh(crow, 128, cc + i)) * 2,
                 Vg + (t * 64 + crow) * H_ + (cc + i) * 8);
        CPCOMMIT();
        CPWAIT(1);         // K(t) (and Q) arrived
        __syncthreads();

        // S = Q @ K^T  (warp 16x32), K=128 in 8 k16 steps
        float sacc[4][4];
#pragma unroll
        for (int nt = 0; nt < 4; nt++)
#pragma unroll
            for (int i = 0; i < 4; i++) sacc[nt][i] = 0.f;

#pragma unroll
        for (int kk = 0; kk < 128; kk += 16) {
            uint32_t aa[4];
            ldsm4(aa, sbase + (uint32_t)(AQ_ + swzh(arow, 128,
                                                    (kk >> 3) + (lane >> 4))) * 2);
#pragma unroll
            for (int p = 0; p < 2; p++) {
                uint32_t bb[4];
                ldsm4(bb, sbase + (uint32_t)(AK_ + swzh(brow + p * 16, 128,
                                                        (kk >> 3) + bksel)) * 2);
                mma_f16(sacc[2 * p],     aa, bb[0], bb[1]);
                mma_f16(sacc[2 * p + 1], aa, bb[2], bb[3]);
            }
        }

        // scale + causal mask in fragment layout
        const bool diag = (t == qt);
#pragma unroll
        for (int nt = 0; nt < 4; nt++) {
            int cn = wns + nt * 8 + tig * 2;
            sacc[nt][0] *= inv_scale;
            sacc[nt][1] *= inv_scale;
            sacc[nt][2] *= inv_scale;
            sacc[nt][3] *= inv_scale;
            if (diag) {
                if (cn > rA)     sacc[nt][0] = -1e30f;
                if (cn + 1 > rA) sacc[nt][1] = -1e30f;
                if (cn > rB)     sacc[nt][2] = -1e30f;
                if (cn + 1 > rB) sacc[nt][3] = -1e30f;
            }
        }

        // row max: quad shfl, then cross-half via smem stats
        float pmaxA = -1e30f, pmaxB = -1e30f;
#pragma unroll
        for (int nt = 0; nt < 4; nt++) {
            pmaxA = fmaxf(pmaxA, fmaxf(sacc[nt][0], sacc[nt][1]));
            pmaxB = fmaxf(pmaxB, fmaxf(sacc[nt][2], sacc[nt][3]));
        }
        pmaxA = fmaxf(pmaxA, __shfl_xor_sync(0xffffffffu, pmaxA, 1));
        pmaxA = fmaxf(pmaxA, __shfl_xor_sync(0xffffffffu, pmaxA, 2));
        pmaxB = fmaxf(pmaxB, __shfl_xor_sync(0xffffffffu, pmaxB, 1));
        pmaxB = fmaxf(pmaxB, __shfl_xor_sync(0xffffffffu, pmaxB, 2));
        if (tig == 0) {
            smS[rA * 4 + half_] = pmaxA;
            smS[rB * 4 + half_] = pmaxB;
        }
        __syncthreads();   // stats visible + all warps done reading smK

        if (t + 1 < t1) {  // prefetch K(t+1), overlaps softmax + PV
#pragma unroll
            for (int i = 0; i < 4; i++)
                CP16(sbase + (uint32_t)(AK_ + swzh(crow, 128, cc + i)) * 2,
                     Kg + ((t + 1) * 64 + crow) * H_ + (cc + i) * 8);
        }
        CPCOMMIT();

        float mxA = fmaxf(pmaxA, smS[rA * 4 + (1 - half_)]);
        float mxB = fmaxf(pmaxB, smS[rB * 4 + (1 - half_)]);
        float mnewA = fmaxf(m_run2[0], mxA);
        float mnewB = fmaxf(m_run2[1], mxB);
        float corrA = __expf(m_run2[0] - mnewA);
        float corrB = __expf(m_run2[1] - mnewB);
        m_run2[0] = mnewA; m_run2[1] = mnewB;

        float psumA = 0.f, psumB = 0.f;
#pragma unroll
        for (int nt = 0; nt < 4; nt++) {
            int cn = wns + nt * 8 + tig * 2;
            float p0 = __expf(sacc[nt][0] - mnewA);
            float p1 = __expf(sacc[nt][1] - mnewA);
            float p2 = __expf(sacc[nt][2] - mnewB);
            float p3 = __expf(sacc[nt][3] - mnewB);
            psumA += p0 + p1;
            psumB += p2 + p3;
            *(__half2*)&smP[swzh(rA, 64, cn >> 3) + (cn & 7)] =
                __floats2half2_rn(p0, p1);
            *(__half2*)&smP[swzh(rB, 64, cn >> 3) + (cn & 7)] =
                __floats2half2_rn(p2, p3);
        }
        psumA += __shfl_xor_sync(0xffffffffu, psumA, 1);
        psumA += __shfl_xor_sync(0xffffffffu, psumA, 2);
        psumB += __shfl_xor_sync(0xffffffffu, psumB, 1);
        psumB += __shfl_xor_sync(0xffffffffu, psumB, 2);
        if (tig == 0) {
            smS[rA * 4 + 2 + half_] = psumA;
            smS[rB * 4 + 2 + half_] = psumB;
        }
        if (t + 1 < t1) { CPWAIT(1); } else { CPWAIT(0); }  // V(t) arrived
        __syncthreads();

        l_run2[0] = l_run2[0] * corrA + psumA + smS[rA * 4 + 2 + (1 - half_)];
        l_run2[1] = l_run2[1] * corrB + psumB + smS[rB * 4 + 2 + (1 - half_)];

        // rescale O, then O += P @ V (warp 16x64), K=64 in 4 k16 steps
#pragma unroll
        for (int nt = 0; nt < 8; nt++) {
            oacc[nt][0] *= corrA; oacc[nt][1] *= corrA;
            oacc[nt][2] *= corrB; oacc[nt][3] *= corrB;
        }
#pragma unroll
        for (int kk = 0; kk < 64; kk += 16) {
            uint32_t aa[4];
            ldsm4(aa, sbase + (uint32_t)(AP_ + swzh(arow, 64,
                                                    (kk >> 3) + (lane >> 4))) * 2);
#pragma unroll
            for (int p = 0; p < 4; p++) {
                uint32_t bb[4];
                int vr = kk + vrow16;
                ldsm4t(bb, sbase + (uint32_t)(AV_ + swzh(vr, 128,
                                        (wno >> 3) + p * 2 + vnsel)) * 2);
                mma_f16(oacc[2 * p],     aa, bb[0], bb[1]);
                mma_f16(oacc[2 * p + 1], aa, bb[2], bb[3]);
            }
        }
    }

    // write unnormalized partials (fp16) + per-row (m, l)
    const int p = idx;
    if (tig == 0 && half_ == 0) {
        g_ml[(p * 64 + rA) * 2 + 0] = m_run2[0];
        g_ml[(p * 64 + rA) * 2 + 1] = l_run2[0];
        g_ml[(p * 64 + rB) * 2 + 0] = m_run2[1];
        g_ml[(p * 64 + rB) * 2 + 1] = l_run2[1];
    }
#pragma unroll
    for (int nt = 0; nt < 8; nt++) {
        int cc2 = wno + nt * 8 + tig * 2;
        *(__half2*)&g_Opart[(p * 64 + rA) * H_ + cc2] =
            __floats2half2_rn(oacc[nt][0], oacc[nt][1]);
        *(__half2*)&g_Opart[(p * 64 + rB) * H_ + cc2] =
            __floats2half2_rn(oacc[nt][2], oacc[nt][3]);
    }
}

// ---------------------------------------------------------------------------
// Kernel 3: merge fp16 partials -> final out.  One float4 per thread.
// ---------------------------------------------------------------------------
__global__ __launch_bounds__(256) void attn_merge(float* __restrict__ out) {
    const int gidx = blockIdx.x * 256 + threadIdx.x;
    const int row = gidx >> 5;           // 0..8191
    const int c0 = (gidx & 31) << 2;     // float4 col
    const int b = row >> 11, rr = row & 2047;
    const int qt = rr >> 6, r = rr & 63;
    const int a = qt >> 2, rm = qt & 3;
    const int nch = a + 1;                       // ceil((qt+1)/4)
    const int ubase = (a + 1) * (2 * a + rm);
    const int pbase = b * UPB + ubase;

    float m = -1e30f;
#pragma unroll 8
    for (int c = 0; c < nch; c++)
        m = fmaxf(m, g_ml[((pbase + c) * 64 + r) * 2]);
    float l = 0.f;
    float ax = 0.f, ay = 0.f, az = 0.f, aw = 0.f;
#pragma unroll 8
    for (int c = 0; c < nch; c++) {
        float wgt = __expf(g_ml[((pbase + c) * 64 + r) * 2] - m);
        l += wgt * g_ml[((pbase + c) * 64 + r) * 2 + 1];
        uint2 raw = *(const uint2*)&g_Opart[((pbase + c) * 64 + r) * H_ + c0];
        float2 f0 = __half22float2(*reinterpret_cast<__half2*>(&raw.x));
        float2 f1 = __half22float2(*reinterpret_cast<__half2*>(&raw.y));
        ax += wgt * f0.x; ay += wgt * f0.y;
        az += wgt * f1.x; aw += wgt * f1.y;
    }
    const float invl = 1.f / l;
    *(float4*)&out[row * H_ + c0] =
        make_float4(ax * invl, ay * invl, az * invl, aw * invl);
}

// ---------------------------------------------------------------------------
// Launch
// ---------------------------------------------------------------------------
extern "C" void kernel_launch(void* const* d_in, const int* in_sizes, int n_in,
                              void* d_out, int out_size) {
    const float* x  = (const float*)d_in[0];
    const float* Wq = (const float*)d_in[1];
    const float* Wk = (const float*)d_in[2];
    const float* Wv = (const float*)d_in[3];
    // d_in[4] = mask: tril by construction -> causal logic used directly.
    float* out = (float*)d_out;

    dim3 gt(C_ / 32, H_ / 32, 3);
    transpose_w<<<gt, dim3(32, 8)>>>(Wq, Wk, Wv);

    cudaFuncSetAttribute((const void*)proj_mma,
                         cudaFuncAttributeMaxDynamicSharedMemorySize, PJ_SMEM);
    proj_mma<<<BT_ / 64, 256, PJ_SMEM>>>(x);

    cudaFuncSetAttribute((const void*)attn_part,
                         cudaFuncAttributeMaxDynamicSharedMemorySize, ATTN_SMEM);
    attn_part<<<NUNITS, 256, ATTN_SMEM>>>();

    attn_merge<<<BT_ * H_ / 4 / 256, 256>>>(out);
}